// round 9
// baseline (speedup 1.0000x reference)
#include <cuda_runtime.h>
#include <stdint.h>

#define T_ 1024
#define B_ 64
#define H_ 256
#define G3 768   // 3*H

typedef unsigned long long ull;

// ---------------- scratch (static device globals; no runtime allocation) ----------------
__device__ float g_xg[(size_t)2 * T_ * G3 * B_];   // [dir][t][n=gate*H+j][b]  (~402 MB)
__device__ float g_y [(size_t)2 * T_ * H_ * B_];   // [dir][t][j][b]           (~128 MB)
// tagged h exchange: [dir][parity][bg][k(256)][b(8)] of (tag<<32 | fp32bits)
__device__ ull   g_ht[2 * 2 * 8 * H_ * 8];         // 512 KB

// f32x2 packed math helpers
__device__ __forceinline__ void fma2(ull& acc, ull a, ull b) {
    asm("fma.rn.f32x2 %0, %1, %2, %0;" : "+l"(acc) : "l"(a), "l"(b));
}
__device__ __forceinline__ float2 u2f(ull v) {
    float2 f;
    f.x = __uint_as_float((unsigned)v);
    f.y = __uint_as_float((unsigned)(v >> 32));
    return f;
}
__device__ __forceinline__ ull ld_relaxed_b64(const ull* p) {
    ull v;
    asm volatile("ld.relaxed.gpu.global.b64 %0, [%1];" : "=l"(v) : "l"(p) : "memory");
    return v;
}
__device__ __forceinline__ void st_relaxed_b64(ull* p, ull v) {
    asm volatile("st.relaxed.gpu.global.b64 [%0], %1;" :: "l"(p), "l"(v) : "memory");
}

// ---------------- init: zero tagged h (tag 0 = step-0 data, h = 0); every replay --------
__global__ void __launch_bounds__(256) init_kernel() {
    int i = blockIdx.x * 256 + threadIdx.x;
    g_ht[i] = 0ull;   // grid sized exactly: 2*2*8*256*8 = 65536
}

// ---------------- phase 1: xg = gather(emb) @ W_ih^T + b_ih, stored transposed [t][n][b] --
__global__ void __launch_bounds__(256) gemm_xg(const int* __restrict__ seq,
                                               const float* __restrict__ emb,
                                               const float* __restrict__ Wf,
                                               const float* __restrict__ Wb,
                                               const float* __restrict__ bf,
                                               const float* __restrict__ bb,
                                               const int* __restrict__ lengths) {
    int id = blockIdx.x;
    int t   = id / 24;
    int r   = id % 24;
    int bt  = r & 1;               // b half-tile
    int nt2 = r >> 1;              // 0..11
    int d   = nt2 / 6;
    int n_base = (nt2 % 6) * 128;

    if (t >= __ldg(&lengths[bt * 32])) return;   // fully-masked tile

    const float* W    = d ? Wb : Wf;
    const float* bias = d ? bb : bf;

    __shared__ float  eT[32][40];
    __shared__ float2 wd2[32 * 128];
    __shared__ int    tok[32];

    int tid = threadIdx.x;
    if (tid < 32) tok[tid] = seq[t * 64 + bt * 32 + tid];

    int nq = tid >> 3, bq = tid & 7;
    int n0 = nq * 4, b0 = bq * 4;

    ull acc[4][2];
#pragma unroll
    for (int i = 0; i < 4; i++) { acc[i][0] = 0ull; acc[i][1] = 0ull; }

    const float4* emb4 = reinterpret_cast<const float4*>(emb);
    const float4* W4   = reinterpret_cast<const float4*>(W);

    for (int k0 = 0; k0 < 256; k0 += 32) {
        __syncthreads();
        {
            int b = tid >> 3, kq = tid & 7;
            float4 v = emb4[(size_t)tok[b] * 64 + (k0 >> 2) + kq];
            eT[kq * 4 + 0][b] = v.x; eT[kq * 4 + 1][b] = v.y;
            eT[kq * 4 + 2][b] = v.z; eT[kq * 4 + 3][b] = v.w;
        }
#pragma unroll
        for (int l = 0; l < 4; l++) {
            int fid = tid + l * 256;
            int n = fid >> 3, kq = fid & 7;
            float4 v = W4[(size_t)(n_base + n) * 64 + (k0 >> 2) + kq];
            wd2[(kq * 4 + 0) * 128 + n] = make_float2(v.x, v.x);
            wd2[(kq * 4 + 1) * 128 + n] = make_float2(v.y, v.y);
            wd2[(kq * 4 + 2) * 128 + n] = make_float2(v.z, v.z);
            wd2[(kq * 4 + 3) * 128 + n] = make_float2(v.w, v.w);
        }
        __syncthreads();
#pragma unroll 8
        for (int kk = 0; kk < 32; kk++) {
            ulonglong2 hh = *reinterpret_cast<const ulonglong2*>(&eT[kk][b0]);
            ulonglong2 w01 = *reinterpret_cast<const ulonglong2*>(&wd2[kk * 128 + n0]);
            ulonglong2 w23 = *reinterpret_cast<const ulonglong2*>(&wd2[kk * 128 + n0 + 2]);
            fma2(acc[0][0], hh.x, w01.x); fma2(acc[0][1], hh.y, w01.x);
            fma2(acc[1][0], hh.x, w01.y); fma2(acc[1][1], hh.y, w01.y);
            fma2(acc[2][0], hh.x, w23.x); fma2(acc[2][1], hh.y, w23.x);
            fma2(acc[3][0], hh.x, w23.y); fma2(acc[3][1], hh.y, w23.y);
        }
    }

    float* out = &g_xg[(size_t)d * T_ * G3 * B_ + (size_t)t * G3 * B_];
#pragma unroll
    for (int i = 0; i < 4; i++) {
        int n = n_base + n0 + i;
        float bv = bias[n];
        float2 lo = u2f(acc[i][0]), hi = u2f(acc[i][1]);
        float4 v;
        v.x = lo.x + bv; v.y = lo.y + bv; v.z = hi.x + bv; v.w = hi.y + bv;
        *reinterpret_cast<float4*>(&out[(size_t)n * 64 + bt * 32 + b0]) = v;
    }
}

// ---------------- phase 2: grouped bidirectional GRU with self-tagged h exchange ---------
// 128 CTAs = dir(2) x bg(8 batch-groups of 8) x r(8 j-groups of 32).
// Each h element carried as (tag<<32 | bits); warp kh waits per 256B line (coalesced),
// retrying ONLY lines whose tags haven't reached this step -> minimal L2 spin traffic.
__global__ void __launch_bounds__(256, 1)
recur_kernel(const float* __restrict__ Whh_f,
             const float* __restrict__ Whh_b,
             const float* __restrict__ bhh_f,
             const float* __restrict__ bhh_b,
             const int* __restrict__ lengths,
             float* __restrict__ out) {
    extern __shared__ float sm[];
    float* red0 = sm;                       // [8][24][33]  6336 floats
    float* red1 = sm + 6336;                // parity double buffer
    float* hsm  = sm + 12672;               // [warp8][b8][36] 2304 floats

    int bid = blockIdx.x;
    int d  = bid >> 6;
    int rm = bid & 63;
    int bg = rm >> 3;       // batch group 0..7
    int r  = rm & 7;        // j group 0..7
    const float* Whh = d ? Whh_b : Whh_f;
    const float* bhh = d ? bhh_b : bhh_f;

    int tid = threadIdx.x;
    // k-loop mapping: warp = k-slice
    int kh = tid >> 5;
    int jl = tid & 31;
    int j  = r * 32 + jl;
    int kbase = kh * 32;
    // gate mapping
    int jl2 = tid >> 3;
    int b2  = tid & 7;
    int j2  = r * 32 + jl2;
    int bglob = bg * 8 + b2;

    // W_hh slice into registers: w[gate][kp] = (W[j][kbase+2kp], W[j][kbase+2kp+1])
    ull w0[16], w1[16], w2[16];
    {
        const ulonglong2* W0 = reinterpret_cast<const ulonglong2*>(
            Whh + (size_t)(0 * 256 + j) * 256 + kbase);
        const ulonglong2* W1 = reinterpret_cast<const ulonglong2*>(
            Whh + (size_t)(1 * 256 + j) * 256 + kbase);
        const ulonglong2* W2 = reinterpret_cast<const ulonglong2*>(
            Whh + (size_t)(2 * 256 + j) * 256 + kbase);
#pragma unroll
        for (int q = 0; q < 8; q++) {
            ulonglong2 v0 = W0[q]; w0[2 * q] = v0.x; w0[2 * q + 1] = v0.y;
            ulonglong2 v1 = W1[q]; w1[2 * q] = v1.x; w1[2 * q + 1] = v1.y;
            ulonglong2 v2 = W2[q]; w2[2 * q] = v2.x; w2[2 * q + 1] = v2.y;
        }
    }
    float br = bhh[0 * 256 + j2];
    float bz = bhh[1 * 256 + j2];
    float bn = bhh[2 * 256 + j2];
    int len_b = lengths[bglob];

    const float* xgbase = &g_xg[(size_t)d * T_ * G3 * B_];
    float* yout = &g_y[(size_t)d * T_ * H_ * B_];
    float* hw = &hsm[kh * 8 * 36];      // this warp's staged slice [b][36]

    float h_reg = 0.f;   // this thread's own h_prev[b2][j2]

    for (int step = 0; step < T_; step++) {
        int t = d ? (T_ - 1 - step) : step;
        int p = step & 1;

        // prefetch xg (independent of h) before any wait
        const float* xg = &xgbase[(size_t)t * G3 * B_];
        float xr = __ldcs(&xg[(size_t)(0 * 256 + j2) * 64 + bglob]);
        float xz = __ldcs(&xg[(size_t)(1 * 256 + j2) * 64 + bglob]);
        float xn = __ldcs(&xg[(size_t)(2 * 256 + j2) * 64 + bglob]);

        // wait on my warp's 2KB tagged slice: PER-LINE retry (only stale lines reloaded)
        const ull* base = &g_ht[(((d * 2 + p) * 8) + bg) * (H_ * 8)] + kbase * 8;
        ull v[8];
        unsigned texp = (unsigned)step;
#pragma unroll
        for (int i = 0; i < 8; i++) {
            v[i] = ld_relaxed_b64(base + i * 32 + jl);
            while (!__all_sync(0xffffffffu, (unsigned)(v[i] >> 32) == texp)) {
                v[i] = ld_relaxed_b64(base + i * 32 + jl);
            }
        }
        // deposit into conflict-free padded smem: n = i*32+jl -> (b = n&7, kk = n>>3)
#pragma unroll
        for (int i = 0; i < 8; i++) {
            int n = i * 32 + jl;
            hw[(n & 7) * 36 + (n >> 3)] = __uint_as_float((unsigned)v[i]);
        }
        __syncwarp();

        // k-slice dot products (broadcast LDS from my warp's staged slice)
        float f[3][8];
#pragma unroll
        for (int b = 0; b < 8; b++) {
            const float4* hp4 = reinterpret_cast<const float4*>(&hw[b * 36]);
            float4 hv4[8];
#pragma unroll
            for (int q = 0; q < 8; q++) hv4[q] = hp4[q];
            const ull* hv = reinterpret_cast<const ull*>(hv4);
            ull a0 = 0ull, a1 = 0ull, a2 = 0ull;
#pragma unroll
            for (int kp = 0; kp < 16; kp++) {
                fma2(a0, hv[kp], w0[kp]);
                fma2(a1, hv[kp], w1[kp]);
                fma2(a2, hv[kp], w2[kp]);
            }
            float2 t0 = u2f(a0), t1 = u2f(a1), t2 = u2f(a2);
            f[0][b] = t0.x + t0.y;
            f[1][b] = t1.x + t1.y;
            f[2][b] = t2.x + t2.y;
        }

        // write partials into parity buffer: red[kh][b*3+g][jl]
        float* redw = p ? red1 : red0;
#pragma unroll
        for (int b = 0; b < 8; b++) {
#pragma unroll
            for (int g = 0; g < 3; g++)
                redw[(kh * 24 + b * 3 + g) * 33 + jl] = f[g][b];
        }
        __syncthreads();   // the ONLY per-step CTA sync

        // gate phase: sum 8 k-slices, apply GRU nonlinearity
        float ar = 0.f, az = 0.f, an = 0.f;
#pragma unroll
        for (int q = 0; q < 8; q++) {
            ar += redw[(q * 24 + b2 * 3 + 0) * 33 + jl2];
            az += redw[(q * 24 + b2 * 3 + 1) * 33 + jl2];
            an += redw[(q * 24 + b2 * 3 + 2) * 33 + jl2];
        }

        float hp = h_reg;
        float rg = 1.f / (1.f + __expf(-(xr + ar + br)));
        float zg = 1.f / (1.f + __expf(-(xz + az + bz)));
        float ng = 2.f / (1.f + __expf(-2.f * (xn + rg * (an + bn)))) - 1.f;
        float hv = ng + zg * (hp - ng);
        bool m = (t < len_b);
        float hnext = m ? hv : hp;
        float yv    = m ? hv : 0.f;
        h_reg = hnext;

        // publish tagged h element FIRST (critical path), then streaming y store
        ull* rowout = &g_ht[(((d * 2 + (p ^ 1)) * 8) + bg) * (H_ * 8)];
        ull tv = ((ull)(unsigned)(step + 1) << 32) | (ull)__float_as_uint(hnext);
        st_relaxed_b64(&rowout[j2 * 8 + b2], tv);

        __stcs(&yout[((size_t)t * H_ + j2) * 64 + bglob], yv);
    }

    // final hidden state (h after all T steps) from register
    out[(size_t)T_ * B_ * H_ + ((size_t)d * 64 + bglob) * 256 + j2] = h_reg;
}

// ---------------- phase 3: outputs = yf + yb (transpose to [t][b][j]) ----------------
__global__ void __launch_bounds__(256) epilogue_kernel(float* __restrict__ out) {
    __shared__ float s[128][65];
    int t = blockIdx.x;
    const float* yf = &g_y[(size_t)0 * T_ * H_ * B_ + (size_t)t * H_ * B_];
    const float* yb = &g_y[(size_t)1 * T_ * H_ * B_ + (size_t)t * H_ * B_];
    for (int half = 0; half < 2; half++) {
        int jofs = half * 128;
        for (int idx = threadIdx.x; idx < 128 * 64; idx += 256) {
            int j = idx >> 6, b = idx & 63;
            size_t o = (size_t)(jofs + j) * 64 + b;
            s[j][b] = yf[o] + yb[o];
        }
        __syncthreads();
        for (int idx = threadIdx.x; idx < 128 * 64; idx += 256) {
            int b = idx >> 7, j = idx & 127;
            out[((size_t)t * 64 + b) * 256 + jofs + j] = s[j][b];
        }
        __syncthreads();
    }
}

// ---------------- launcher ----------------
extern "C" void kernel_launch(void* const* d_in, const int* in_sizes, int n_in,
                              void* d_out, int out_size) {
    const int*   seq  = (const int*)  d_in[0];
    const int*   lens = (const int*)  d_in[1];
    const float* emb  = (const float*)d_in[2];
    const float* Wihf = (const float*)d_in[3];
    const float* Whhf = (const float*)d_in[4];
    const float* bihf = (const float*)d_in[5];
    const float* bhhf = (const float*)d_in[6];
    const float* Wihb = (const float*)d_in[7];
    const float* Whhb = (const float*)d_in[8];
    const float* bihb = (const float*)d_in[9];
    const float* bhhb = (const float*)d_in[10];
    float* out = (float*)d_out;

    const int smem_recur = (2 * 6336 + 2304) * 4;   // 59904 B
    cudaFuncSetAttribute(recur_kernel, cudaFuncAttributeMaxDynamicSharedMemorySize, smem_recur);

    init_kernel<<<256, 256>>>();
    gemm_xg<<<T_ * 24, 256>>>(seq, emb, Wihf, Wihb, bihf, bihb, lens);
    recur_kernel<<<128, 256, smem_recur>>>(Whhf, Whhb, bhhf, bhhb, lens, out);
    epilogue_kernel<<<T_, 256>>>(out);
}

// round 10
// speedup vs baseline: 1.1926x; 1.1926x over previous
#include <cuda_runtime.h>
#include <stdint.h>

#define T_ 1024
#define B_ 64
#define H_ 256
#define G3 768   // 3*H

typedef unsigned long long ull;

// ---------------- scratch (static device globals; no runtime allocation) ----------------
__device__ float g_xg[(size_t)2 * T_ * G3 * B_];   // [dir][t][n=gate*H+j][b]  (~402 MB)
__device__ float g_y [(size_t)2 * T_ * H_ * B_];   // [dir][t][j][b]           (~128 MB)
// tagged h exchange: [dir][parity][bg][k(256)][b(8)] of (tag<<32 | fp32bits)
__device__ ull   g_ht[2 * 2 * 8 * H_ * 8];         // 512 KB

// f32x2 packed math helpers
__device__ __forceinline__ void fma2(ull& acc, ull a, ull b) {
    asm("fma.rn.f32x2 %0, %1, %2, %0;" : "+l"(acc) : "l"(a), "l"(b));
}
__device__ __forceinline__ float2 u2f(ull v) {
    float2 f;
    f.x = __uint_as_float((unsigned)v);
    f.y = __uint_as_float((unsigned)(v >> 32));
    return f;
}
__device__ __forceinline__ ull ld_relaxed_b64(const ull* p) {
    ull v;
    asm volatile("ld.relaxed.gpu.global.b64 %0, [%1];" : "=l"(v) : "l"(p) : "memory");
    return v;
}
__device__ __forceinline__ void st_relaxed_b64(ull* p, ull v) {
    asm volatile("st.relaxed.gpu.global.b64 [%0], %1;" :: "l"(p), "l"(v) : "memory");
}

// ---------------- init: zero tagged h (tag 0 = step-0 data, h = 0); every replay --------
__global__ void __launch_bounds__(256) init_kernel() {
    int i = blockIdx.x * 256 + threadIdx.x;
    g_ht[i] = 0ull;   // grid sized exactly: 2*2*8*256*8 = 65536
}

// ---------------- phase 1: xg = gather(emb) @ W_ih^T + b_ih, stored transposed [t][n][b] --
__global__ void __launch_bounds__(256) gemm_xg(const int* __restrict__ seq,
                                               const float* __restrict__ emb,
                                               const float* __restrict__ Wf,
                                               const float* __restrict__ Wb,
                                               const float* __restrict__ bf,
                                               const float* __restrict__ bb,
                                               const int* __restrict__ lengths) {
    int id = blockIdx.x;
    int t   = id / 24;
    int r   = id % 24;
    int bt  = r & 1;               // b half-tile
    int nt2 = r >> 1;              // 0..11
    int d   = nt2 / 6;
    int n_base = (nt2 % 6) * 128;

    if (t >= __ldg(&lengths[bt * 32])) return;   // fully-masked tile

    const float* W    = d ? Wb : Wf;
    const float* bias = d ? bb : bf;

    __shared__ float  eT[32][40];
    __shared__ float2 wd2[32 * 128];
    __shared__ int    tok[32];

    int tid = threadIdx.x;
    if (tid < 32) tok[tid] = seq[t * 64 + bt * 32 + tid];

    int nq = tid >> 3, bq = tid & 7;
    int n0 = nq * 4, b0 = bq * 4;

    ull acc[4][2];
#pragma unroll
    for (int i = 0; i < 4; i++) { acc[i][0] = 0ull; acc[i][1] = 0ull; }

    const float4* emb4 = reinterpret_cast<const float4*>(emb);
    const float4* W4   = reinterpret_cast<const float4*>(W);

    for (int k0 = 0; k0 < 256; k0 += 32) {
        __syncthreads();
        {
            int b = tid >> 3, kq = tid & 7;
            float4 v = emb4[(size_t)tok[b] * 64 + (k0 >> 2) + kq];
            eT[kq * 4 + 0][b] = v.x; eT[kq * 4 + 1][b] = v.y;
            eT[kq * 4 + 2][b] = v.z; eT[kq * 4 + 3][b] = v.w;
        }
#pragma unroll
        for (int l = 0; l < 4; l++) {
            int fid = tid + l * 256;
            int n = fid >> 3, kq = fid & 7;
            float4 v = W4[(size_t)(n_base + n) * 64 + (k0 >> 2) + kq];
            wd2[(kq * 4 + 0) * 128 + n] = make_float2(v.x, v.x);
            wd2[(kq * 4 + 1) * 128 + n] = make_float2(v.y, v.y);
            wd2[(kq * 4 + 2) * 128 + n] = make_float2(v.z, v.z);
            wd2[(kq * 4 + 3) * 128 + n] = make_float2(v.w, v.w);
        }
        __syncthreads();
#pragma unroll 8
        for (int kk = 0; kk < 32; kk++) {
            ulonglong2 hh = *reinterpret_cast<const ulonglong2*>(&eT[kk][b0]);
            ulonglong2 w01 = *reinterpret_cast<const ulonglong2*>(&wd2[kk * 128 + n0]);
            ulonglong2 w23 = *reinterpret_cast<const ulonglong2*>(&wd2[kk * 128 + n0 + 2]);
            fma2(acc[0][0], hh.x, w01.x); fma2(acc[0][1], hh.y, w01.x);
            fma2(acc[1][0], hh.x, w01.y); fma2(acc[1][1], hh.y, w01.y);
            fma2(acc[2][0], hh.x, w23.x); fma2(acc[2][1], hh.y, w23.x);
            fma2(acc[3][0], hh.x, w23.y); fma2(acc[3][1], hh.y, w23.y);
        }
    }

    float* out = &g_xg[(size_t)d * T_ * G3 * B_ + (size_t)t * G3 * B_];
#pragma unroll
    for (int i = 0; i < 4; i++) {
        int n = n_base + n0 + i;
        float bv = bias[n];
        float2 lo = u2f(acc[i][0]), hi = u2f(acc[i][1]);
        float4 v;
        v.x = lo.x + bv; v.y = lo.y + bv; v.z = hi.x + bv; v.w = hi.y + bv;
        *reinterpret_cast<float4*>(&out[(size_t)n * 64 + bt * 32 + b0]) = v;
    }
}

// ---------------- phase 2: grouped bidirectional GRU with self-tagged h exchange ---------
// 128 CTAs = dir(2) x bg(8 batch-groups of 8) x r(8 j-groups of 32).
// Each h element carried as (tag<<32 | bits); warp kh spins on its 2KB slice with an
// MLP-preserving selective retry: every round issues loads for ALL stale lines in
// parallel, then retires validated lines from the pending mask (warp-uniform).
__global__ void __launch_bounds__(256, 1)
recur_kernel(const float* __restrict__ Whh_f,
             const float* __restrict__ Whh_b,
             const float* __restrict__ bhh_f,
             const float* __restrict__ bhh_b,
             const int* __restrict__ lengths,
             float* __restrict__ out) {
    extern __shared__ float sm[];
    float* red0 = sm;                       // [8][24][33]  6336 floats
    float* red1 = sm + 6336;                // parity double buffer
    float* hsm  = sm + 12672;               // [warp8][b8][36] 2304 floats

    int bid = blockIdx.x;
    int d  = bid >> 6;
    int rm = bid & 63;
    int bg = rm >> 3;       // batch group 0..7
    int r  = rm & 7;        // j group 0..7
    const float* Whh = d ? Whh_b : Whh_f;
    const float* bhh = d ? bhh_b : bhh_f;

    int tid = threadIdx.x;
    // k-loop mapping: warp = k-slice
    int kh = tid >> 5;
    int jl = tid & 31;
    int j  = r * 32 + jl;
    int kbase = kh * 32;
    // gate mapping
    int jl2 = tid >> 3;
    int b2  = tid & 7;
    int j2  = r * 32 + jl2;
    int bglob = bg * 8 + b2;

    // W_hh slice into registers: w[gate][kp] = (W[j][kbase+2kp], W[j][kbase+2kp+1])
    ull w0[16], w1[16], w2[16];
    {
        const ulonglong2* W0 = reinterpret_cast<const ulonglong2*>(
            Whh + (size_t)(0 * 256 + j) * 256 + kbase);
        const ulonglong2* W1 = reinterpret_cast<const ulonglong2*>(
            Whh + (size_t)(1 * 256 + j) * 256 + kbase);
        const ulonglong2* W2 = reinterpret_cast<const ulonglong2*>(
            Whh + (size_t)(2 * 256 + j) * 256 + kbase);
#pragma unroll
        for (int q = 0; q < 8; q++) {
            ulonglong2 v0 = W0[q]; w0[2 * q] = v0.x; w0[2 * q + 1] = v0.y;
            ulonglong2 v1 = W1[q]; w1[2 * q] = v1.x; w1[2 * q + 1] = v1.y;
            ulonglong2 v2 = W2[q]; w2[2 * q] = v2.x; w2[2 * q + 1] = v2.y;
        }
    }
    float br = bhh[0 * 256 + j2];
    float bz = bhh[1 * 256 + j2];
    float bn = bhh[2 * 256 + j2];
    int len_b = lengths[bglob];

    const float* xgbase = &g_xg[(size_t)d * T_ * G3 * B_];
    float* yout = &g_y[(size_t)d * T_ * H_ * B_];
    float* hw = &hsm[kh * 8 * 36];      // this warp's staged slice [b][36]

    float h_reg = 0.f;   // this thread's own h_prev[b2][j2]

    for (int step = 0; step < T_; step++) {
        int t = d ? (T_ - 1 - step) : step;
        int p = step & 1;

        // prefetch xg (independent of h) before any wait
        const float* xg = &xgbase[(size_t)t * G3 * B_];
        float xr = __ldcs(&xg[(size_t)(0 * 256 + j2) * 64 + bglob]);
        float xz = __ldcs(&xg[(size_t)(1 * 256 + j2) * 64 + bglob]);
        float xn = __ldcs(&xg[(size_t)(2 * 256 + j2) * 64 + bglob]);

        // wait on my warp's 2KB tagged slice: selective retry, MLP preserved.
        // Each round issues loads for ALL pending lines (independent => overlapped),
        // then retires validated lines. pend is warp-uniform (vote-derived).
        const ull* base = &g_ht[(((d * 2 + p) * 8) + bg) * (H_ * 8)] + kbase * 8;
        ull v[8];
        unsigned texp = (unsigned)step;
        unsigned pend = 0xFFu;
        do {
#pragma unroll
            for (int i = 0; i < 8; i++)
                if (pend & (1u << i)) v[i] = ld_relaxed_b64(base + i * 32 + jl);
#pragma unroll
            for (int i = 0; i < 8; i++)
                if (pend & (1u << i))
                    if (__all_sync(0xffffffffu, (unsigned)(v[i] >> 32) == texp))
                        pend &= ~(1u << i);
        } while (pend);

        // deposit into conflict-free padded smem: n = i*32+jl -> (b = n&7, kk = n>>3)
#pragma unroll
        for (int i = 0; i < 8; i++) {
            int n = i * 32 + jl;
            hw[(n & 7) * 36 + (n >> 3)] = __uint_as_float((unsigned)v[i]);
        }
        __syncwarp();

        // k-slice dot products (broadcast LDS from my warp's staged slice)
        float f[3][8];
#pragma unroll
        for (int b = 0; b < 8; b++) {
            const float4* hp4 = reinterpret_cast<const float4*>(&hw[b * 36]);
            float4 hv4[8];
#pragma unroll
            for (int q = 0; q < 8; q++) hv4[q] = hp4[q];
            const ull* hv = reinterpret_cast<const ull*>(hv4);
            ull a0 = 0ull, a1 = 0ull, a2 = 0ull;
#pragma unroll
            for (int kp = 0; kp < 16; kp++) {
                fma2(a0, hv[kp], w0[kp]);
                fma2(a1, hv[kp], w1[kp]);
                fma2(a2, hv[kp], w2[kp]);
            }
            float2 t0 = u2f(a0), t1 = u2f(a1), t2 = u2f(a2);
            f[0][b] = t0.x + t0.y;
            f[1][b] = t1.x + t1.y;
            f[2][b] = t2.x + t2.y;
        }

        // write partials into parity buffer: red[kh][b*3+g][jl]
        float* redw = p ? red1 : red0;
#pragma unroll
        for (int b = 0; b < 8; b++) {
#pragma unroll
            for (int g = 0; g < 3; g++)
                redw[(kh * 24 + b * 3 + g) * 33 + jl] = f[g][b];
        }
        __syncthreads();   // the ONLY per-step CTA sync

        // gate phase: sum 8 k-slices, apply GRU nonlinearity
        float ar = 0.f, az = 0.f, an = 0.f;
#pragma unroll
        for (int q = 0; q < 8; q++) {
            ar += redw[(q * 24 + b2 * 3 + 0) * 33 + jl2];
            az += redw[(q * 24 + b2 * 3 + 1) * 33 + jl2];
            an += redw[(q * 24 + b2 * 3 + 2) * 33 + jl2];
        }

        float hp = h_reg;
        float rg = 1.f / (1.f + __expf(-(xr + ar + br)));
        float zg = 1.f / (1.f + __expf(-(xz + az + bz)));
        float ng = 2.f / (1.f + __expf(-2.f * (xn + rg * (an + bn)))) - 1.f;
        float hv = ng + zg * (hp - ng);
        bool m = (t < len_b);
        float hnext = m ? hv : hp;
        float yv    = m ? hv : 0.f;
        h_reg = hnext;

        // publish tagged h element (value + tag in one atomic 8B word)
        ull* rowout = &g_ht[(((d * 2 + (p ^ 1)) * 8) + bg) * (H_ * 8)];
        ull tv = ((ull)(unsigned)(step + 1) << 32) | (ull)__float_as_uint(hnext);
        st_relaxed_b64(&rowout[j2 * 8 + b2], tv);

        yout[((size_t)t * H_ + j2) * 64 + bglob] = yv;
        if (step == T_ - 1) {
            out[(size_t)T_ * B_ * H_ + ((size_t)d * 64 + bglob) * 256 + j2] = hnext;
        }
    }
}

// ---------------- phase 3: outputs = yf + yb (transpose to [t][b][j]) ----------------
__global__ void __launch_bounds__(256) epilogue_kernel(float* __restrict__ out) {
    __shared__ float s[128][65];
    int t = blockIdx.x;
    const float* yf = &g_y[(size_t)0 * T_ * H_ * B_ + (size_t)t * H_ * B_];
    const float* yb = &g_y[(size_t)1 * T_ * H_ * B_ + (size_t)t * H_ * B_];
    for (int half = 0; half < 2; half++) {
        int jofs = half * 128;
        for (int idx = threadIdx.x; idx < 128 * 64; idx += 256) {
            int j = idx >> 6, b = idx & 63;
            size_t o = (size_t)(jofs + j) * 64 + b;
            s[j][b] = yf[o] + yb[o];
        }
        __syncthreads();
        for (int idx = threadIdx.x; idx < 128 * 64; idx += 256) {
            int b = idx >> 7, j = idx & 127;
            out[((size_t)t * 64 + b) * 256 + jofs + j] = s[j][b];
        }
        __syncthreads();
    }
}

// ---------------- launcher ----------------
extern "C" void kernel_launch(void* const* d_in, const int* in_sizes, int n_in,
                              void* d_out, int out_size) {
    const int*   seq  = (const int*)  d_in[0];
    const int*   lens = (const int*)  d_in[1];
    const float* emb  = (const float*)d_in[2];
    const float* Wihf = (const float*)d_in[3];
    const float* Whhf = (const float*)d_in[4];
    const float* bihf = (const float*)d_in[5];
    const float* bhhf = (const float*)d_in[6];
    const float* Wihb = (const float*)d_in[7];
    const float* Whhb = (const float*)d_in[8];
    const float* bihb = (const float*)d_in[9];
    const float* bhhb = (const float*)d_in[10];
    float* out = (float*)d_out;

    const int smem_recur = (2 * 6336 + 2304) * 4;   // 59904 B
    cudaFuncSetAttribute(recur_kernel, cudaFuncAttributeMaxDynamicSharedMemorySize, smem_recur);

    init_kernel<<<256, 256>>>();
    gemm_xg<<<T_ * 24, 256>>>(seq, emb, Wihf, Wihb, bihf, bihb, lens);
    recur_kernel<<<128, 256, smem_recur>>>(Whhf, Whhb, bhhf, bhhb, lens, out);
    epilogue_kernel<<<T_, 256>>>(out);
}

// round 14
// speedup vs baseline: 1.2487x; 1.0471x over previous
#include <cuda_runtime.h>
#include <stdint.h>

#define T_ 1024
#define B_ 64
#define H_ 256
#define G3 768   // 3*H

typedef unsigned long long ull;

// ---------------- scratch (static device globals; no runtime allocation) ----------------
__device__ float g_xg[(size_t)2 * T_ * G3 * B_];   // [dir][t][n=gate*H+j][b]  (~402 MB)
// tagged h exchange: [dir][parity][bg][k(256)][b(8)] of (tag<<32 | fp32bits)
__device__ ull   g_ht[2 * 2 * 8 * H_ * 8];         // 512 KB

// f32x2 packed math helpers
__device__ __forceinline__ void fma2(ull& acc, ull a, ull b) {
    asm("fma.rn.f32x2 %0, %1, %2, %0;" : "+l"(acc) : "l"(a), "l"(b));
}
__device__ __forceinline__ float2 u2f(ull v) {
    float2 f;
    f.x = __uint_as_float((unsigned)v);
    f.y = __uint_as_float((unsigned)(v >> 32));
    return f;
}
__device__ __forceinline__ ull ld_relaxed_b64(const ull* p) {
    ull v;
    asm volatile("ld.relaxed.gpu.global.b64 %0, [%1];" : "=l"(v) : "l"(p) : "memory");
    return v;
}
__device__ __forceinline__ void st_relaxed_b64(ull* p, ull v) {
    asm volatile("st.relaxed.gpu.global.b64 [%0], %1;" :: "l"(p), "l"(v) : "memory");
}

// ---------------- init: zero tagged h + y-region of out; MUST run every call (replays) ---
__global__ void __launch_bounds__(256) init_kernel(float* __restrict__ out) {
    int i = blockIdx.x * 256 + threadIdx.x;          // grid 8192 x 256 = 2,097,152 threads
    if (i < 2 * 2 * 8 * H_ * 8) g_ht[i] = 0ull;      // 65536 words
    // zero out[0 : T*B*H) = 16,777,216 floats = 4,194,304 float4, 2 per thread
    float4* o4 = reinterpret_cast<float4*>(out);
    float4 z = make_float4(0.f, 0.f, 0.f, 0.f);
    o4[i] = z;
    o4[i + 2097152] = z;
}

// ---------------- phase 1: xg = gather(emb) @ W_ih^T + b_ih, stored transposed [t][n][b] --
__global__ void __launch_bounds__(256) gemm_xg(const int* __restrict__ seq,
                                               const float* __restrict__ emb,
                                               const float* __restrict__ Wf,
                                               const float* __restrict__ Wb,
                                               const float* __restrict__ bf,
                                               const float* __restrict__ bb,
                                               const int* __restrict__ lengths) {
    int id = blockIdx.x;
    int t   = id / 24;
    int r   = id % 24;
    int bt  = r & 1;               // b half-tile
    int nt2 = r >> 1;              // 0..11
    int d   = nt2 / 6;
    int n_base = (nt2 % 6) * 128;

    if (t >= __ldg(&lengths[bt * 32])) return;   // fully-masked tile

    const float* W    = d ? Wb : Wf;
    const float* bias = d ? bb : bf;

    __shared__ float  eT[32][40];
    __shared__ float2 wd2[32 * 128];
    __shared__ int    tok[32];

    int tid = threadIdx.x;
    if (tid < 32) tok[tid] = seq[t * 64 + bt * 32 + tid];

    int nq = tid >> 3, bq = tid & 7;
    int n0 = nq * 4, b0 = bq * 4;

    ull acc[4][2];
#pragma unroll
    for (int i = 0; i < 4; i++) { acc[i][0] = 0ull; acc[i][1] = 0ull; }

    const float4* emb4 = reinterpret_cast<const float4*>(emb);
    const float4* W4   = reinterpret_cast<const float4*>(W);

    for (int k0 = 0; k0 < 256; k0 += 32) {
        __syncthreads();
        {
            int b = tid >> 3, kq = tid & 7;
            float4 v = emb4[(size_t)tok[b] * 64 + (k0 >> 2) + kq];
            eT[kq * 4 + 0][b] = v.x; eT[kq * 4 + 1][b] = v.y;
            eT[kq * 4 + 2][b] = v.z; eT[kq * 4 + 3][b] = v.w;
        }
#pragma unroll
        for (int l = 0; l < 4; l++) {
            int fid = tid + l * 256;
            int n = fid >> 3, kq = fid & 7;
            float4 v = W4[(size_t)(n_base + n) * 64 + (k0 >> 2) + kq];
            wd2[(kq * 4 + 0) * 128 + n] = make_float2(v.x, v.x);
            wd2[(kq * 4 + 1) * 128 + n] = make_float2(v.y, v.y);
            wd2[(kq * 4 + 2) * 128 + n] = make_float2(v.z, v.z);
            wd2[(kq * 4 + 3) * 128 + n] = make_float2(v.w, v.w);
        }
        __syncthreads();
#pragma unroll 8
        for (int kk = 0; kk < 32; kk++) {
            ulonglong2 hh = *reinterpret_cast<const ulonglong2*>(&eT[kk][b0]);
            ulonglong2 w01 = *reinterpret_cast<const ulonglong2*>(&wd2[kk * 128 + n0]);
            ulonglong2 w23 = *reinterpret_cast<const ulonglong2*>(&wd2[kk * 128 + n0 + 2]);
            fma2(acc[0][0], hh.x, w01.x); fma2(acc[0][1], hh.y, w01.x);
            fma2(acc[1][0], hh.x, w01.y); fma2(acc[1][1], hh.y, w01.y);
            fma2(acc[2][0], hh.x, w23.x); fma2(acc[2][1], hh.y, w23.x);
            fma2(acc[3][0], hh.x, w23.y); fma2(acc[3][1], hh.y, w23.y);
        }
    }

    float* out = &g_xg[(size_t)d * T_ * G3 * B_ + (size_t)t * G3 * B_];
#pragma unroll
    for (int i = 0; i < 4; i++) {
        int n = n_base + n0 + i;
        float bv = bias[n];
        float2 lo = u2f(acc[i][0]), hi = u2f(acc[i][1]);
        float4 v;
        v.x = lo.x + bv; v.y = lo.y + bv; v.z = hi.x + bv; v.w = hi.y + bv;
        // streaming store: xg is written once, read once much later -> keep out of L2
        __stcs(reinterpret_cast<float4*>(&out[(size_t)n * 64 + bt * 32 + b0]), v);
    }
}

// ---------------- phase 2: grouped bidirectional GRU with self-tagged h exchange ---------
// 128 CTAs = dir(2) x bg(8 batch-groups of 8) x r(8 j-groups of 32).
// Each h element carried as (tag<<32 | bits); warp kh spins on COALESCED reloads of its
// 2KB slice (R8-proven shape). y written directly into out via atomicAdd (fwd+bwd each
// contribute once per element; out zeroed by init -> order-independent, bit-deterministic).
__global__ void __launch_bounds__(256, 1)
recur_kernel(const float* __restrict__ Whh_f,
             const float* __restrict__ Whh_b,
             const float* __restrict__ bhh_f,
             const float* __restrict__ bhh_b,
             const int* __restrict__ lengths,
             float* __restrict__ out) {
    extern __shared__ float sm[];
    float* red0 = sm;                       // [8][24][33]  6336 floats
    float* red1 = sm + 6336;                // parity double buffer
    float* hsm  = sm + 12672;               // [warp8][b8][36] 2304 floats

    int bid = blockIdx.x;
    int d  = bid >> 6;
    int rm = bid & 63;
    int bg = rm >> 3;       // batch group 0..7
    int r  = rm & 7;        // j group 0..7
    const float* Whh = d ? Whh_b : Whh_f;
    const float* bhh = d ? bhh_b : bhh_f;

    int tid = threadIdx.x;
    // k-loop mapping: warp = k-slice
    int kh = tid >> 5;
    int jl = tid & 31;
    int j  = r * 32 + jl;
    int kbase = kh * 32;
    // gate mapping
    int jl2 = tid >> 3;
    int b2  = tid & 7;
    int j2  = r * 32 + jl2;
    int bglob = bg * 8 + b2;

    // W_hh slice into registers: w[gate][kp] = (W[j][kbase+2kp], W[j][kbase+2kp+1])
    ull w0[16], w1[16], w2[16];
    {
        const ulonglong2* W0 = reinterpret_cast<const ulonglong2*>(
            Whh + (size_t)(0 * 256 + j) * 256 + kbase);
        const ulonglong2* W1 = reinterpret_cast<const ulonglong2*>(
            Whh + (size_t)(1 * 256 + j) * 256 + kbase);
        const ulonglong2* W2 = reinterpret_cast<const ulonglong2*>(
            Whh + (size_t)(2 * 256 + j) * 256 + kbase);
#pragma unroll
        for (int q = 0; q < 8; q++) {
            ulonglong2 v0 = W0[q]; w0[2 * q] = v0.x; w0[2 * q + 1] = v0.y;
            ulonglong2 v1 = W1[q]; w1[2 * q] = v1.x; w1[2 * q + 1] = v1.y;
            ulonglong2 v2 = W2[q]; w2[2 * q] = v2.x; w2[2 * q + 1] = v2.y;
        }
    }
    float br = bhh[0 * 256 + j2];
    float bz = bhh[1 * 256 + j2];
    float bn = bhh[2 * 256 + j2];
    int len_b = lengths[bglob];

    const float* xgbase = &g_xg[(size_t)d * T_ * G3 * B_];
    float* hw = &hsm[kh * 8 * 36];      // this warp's staged slice [b][36]

    float h_reg = 0.f;   // this thread's own h_prev[b2][j2]

    for (int step = 0; step < T_; step++) {
        int t = d ? (T_ - 1 - step) : step;
        int p = step & 1;

        // prefetch xg (independent of h) before any wait
        const float* xg = &xgbase[(size_t)t * G3 * B_];
        float xr = __ldcs(&xg[(size_t)(0 * 256 + j2) * 64 + bglob]);
        float xz = __ldcs(&xg[(size_t)(1 * 256 + j2) * 64 + bglob]);
        float xn = __ldcs(&xg[(size_t)(2 * 256 + j2) * 64 + bglob]);

        // spin on my warp's 2KB tagged slice (8 coalesced 256B loads per round; R8 shape)
        const ull* base = &g_ht[(((d * 2 + p) * 8) + bg) * (H_ * 8)] + kbase * 8;
        ull v[8];
        unsigned texp = (unsigned)step;
        for (;;) {
#pragma unroll
            for (int i = 0; i < 8; i++) v[i] = ld_relaxed_b64(base + i * 32 + jl);
            unsigned ok = 1u;
#pragma unroll
            for (int i = 0; i < 8; i++) ok &= (unsigned)((unsigned)(v[i] >> 32) == texp);
            if (__all_sync(0xffffffffu, ok)) break;
        }
        // deposit into conflict-free padded smem: n = i*32+jl -> (b = n&7, kk = n>>3)
#pragma unroll
        for (int i = 0; i < 8; i++) {
            int n = i * 32 + jl;
            hw[(n & 7) * 36 + (n >> 3)] = __uint_as_float((unsigned)v[i]);
        }
        __syncwarp();

        // k-slice dot products (broadcast LDS from my warp's staged slice)
        float f[3][8];
#pragma unroll
        for (int b = 0; b < 8; b++) {
            const float4* hp4 = reinterpret_cast<const float4*>(&hw[b * 36]);
            float4 hv4[8];
#pragma unroll
            for (int q = 0; q < 8; q++) hv4[q] = hp4[q];
            const ull* hv = reinterpret_cast<const ull*>(hv4);
            ull a0 = 0ull, a1 = 0ull, a2 = 0ull;
#pragma unroll
            for (int kp = 0; kp < 16; kp++) {
                fma2(a0, hv[kp], w0[kp]);
                fma2(a1, hv[kp], w1[kp]);
                fma2(a2, hv[kp], w2[kp]);
            }
            float2 t0 = u2f(a0), t1 = u2f(a1), t2 = u2f(a2);
            f[0][b] = t0.x + t0.y;
            f[1][b] = t1.x + t1.y;
            f[2][b] = t2.x + t2.y;
        }

        // write partials into parity buffer: red[kh][b*3+g][jl]
        float* redw = p ? red1 : red0;
#pragma unroll
        for (int b = 0; b < 8; b++) {
#pragma unroll
            for (int g = 0; g < 3; g++)
                redw[(kh * 24 + b * 3 + g) * 33 + jl] = f[g][b];
        }
        __syncthreads();   // the ONLY per-step CTA sync

        // gate phase: sum 8 k-slices, apply GRU nonlinearity
        float ar = 0.f, az = 0.f, an = 0.f;
#pragma unroll
        for (int q = 0; q < 8; q++) {
            ar += redw[(q * 24 + b2 * 3 + 0) * 33 + jl2];
            az += redw[(q * 24 + b2 * 3 + 1) * 33 + jl2];
            an += redw[(q * 24 + b2 * 3 + 2) * 33 + jl2];
        }

        float hp = h_reg;
        float rg = 1.f / (1.f + __expf(-(xr + ar + br)));
        float zg = 1.f / (1.f + __expf(-(xz + az + bz)));
        float ng = 2.f / (1.f + __expf(-2.f * (xn + rg * (an + bn)))) - 1.f;
        float hv = ng + zg * (hp - ng);
        bool m = (t < len_b);
        float hnext = m ? hv : hp;
        h_reg = hnext;

        // publish tagged h element FIRST (critical path)
        ull* rowout = &g_ht[(((d * 2 + (p ^ 1)) * 8) + bg) * (H_ * 8)];
        ull tv = ((ull)(unsigned)(step + 1) << 32) | (ull)__float_as_uint(hnext);
        st_relaxed_b64(&rowout[j2 * 8 + b2], tv);

        // y contribution straight into out (fwd+bwd each add once; masked adds skipped)
        if (m) atomicAdd(&out[((size_t)t * 64 + bglob) * 256 + j2], hv);
    }

    // final hidden state (h after all T steps)
    out[(size_t)T_ * B_ * H_ + ((size_t)d * 64 + bglob) * 256 + j2] = h_reg;
}

// ---------------- launcher: init -> gemm -> recur (single stream, graph-safe) ----------
extern "C" void kernel_launch(void* const* d_in, const int* in_sizes, int n_in,
                              void* d_out, int out_size) {
    const int*   seq  = (const int*)  d_in[0];
    const int*   lens = (const int*)  d_in[1];
    const float* emb  = (const float*)d_in[2];
    const float* Wihf = (const float*)d_in[3];
    const float* Whhf = (const float*)d_in[4];
    const float* bihf = (const float*)d_in[5];
    const float* bhhf = (const float*)d_in[6];
    const float* Wihb = (const float*)d_in[7];
    const float* Whhb = (const float*)d_in[8];
    const float* bihb = (const float*)d_in[9];
    const float* bhhb = (const float*)d_in[10];
    float* out = (float*)d_out;

    const int smem_recur = (2 * 6336 + 2304) * 4;   // 59904 B
    cudaFuncSetAttribute(recur_kernel, cudaFuncAttributeMaxDynamicSharedMemorySize, smem_recur);

    init_kernel<<<8192, 256>>>(out);
    gemm_xg<<<T_ * 24, 256>>>(seq, emb, Wihf, Wihb, bihf, bihb, lens);
    recur_kernel<<<128, 256, smem_recur>>>(Whhf, Whhb, bhhf, bhhb, lens, out);
}

// round 15
// speedup vs baseline: 1.2909x; 1.0338x over previous
#include <cuda_runtime.h>
#include <stdint.h>

#define T_ 1024
#define B_ 64
#define H_ 256
#define G3 768   // 3*H

typedef unsigned long long ull;

// ---------------- scratch (static device globals; no runtime allocation) ----------------
__device__ float g_xg[(size_t)2 * T_ * G3 * B_];   // [dir][t][n=gate*H+j][b]  (~402 MB)
// tagged h exchange: [dir][parity][bg][k(256)][b(8)] of (tag<<32 | fp32bits)
__device__ ull   g_ht[2 * 2 * 8 * H_ * 8];         // 512 KB

// f32x2 packed math helpers
__device__ __forceinline__ void fma2(ull& acc, ull a, ull b) {
    asm("fma.rn.f32x2 %0, %1, %2, %0;" : "+l"(acc) : "l"(a), "l"(b));
}
__device__ __forceinline__ float2 u2f(ull v) {
    float2 f;
    f.x = __uint_as_float((unsigned)v);
    f.y = __uint_as_float((unsigned)(v >> 32));
    return f;
}
__device__ __forceinline__ ull ld_relaxed_b64(const ull* p) {
    ull v;
    asm volatile("ld.relaxed.gpu.global.b64 %0, [%1];" : "=l"(v) : "l"(p) : "memory");
    return v;
}
__device__ __forceinline__ void st_relaxed_b64(ull* p, ull v) {
    asm volatile("st.relaxed.gpu.global.b64 [%0], %1;" :: "l"(p), "l"(v) : "memory");
}

// ---------------- init: zero tagged h + y-region of out; MUST run every call (replays) ---
__global__ void __launch_bounds__(256) init_kernel(float* __restrict__ out) {
    int i = blockIdx.x * 256 + threadIdx.x;          // grid 8192 x 256 = 2,097,152 threads
    if (i < 2 * 2 * 8 * H_ * 8) g_ht[i] = 0ull;      // 65536 words
    // zero out[0 : T*B*H) = 16,777,216 floats = 4,194,304 float4, 2 per thread
    float4* o4 = reinterpret_cast<float4*>(out);
    float4 z = make_float4(0.f, 0.f, 0.f, 0.f);
    o4[i] = z;
    o4[i + 2097152] = z;
}

// ---------------- phase 1: xg = gather(emb) @ W_ih^T + b_ih, stored transposed [t][n][b] --
// 64-thread blocks, block tile 128n x 32b, per-thread tile 8n x 8b (register-blocked:
// 6 LDS.128 per 32 FFMA2 -> FMA-pipe-bound instead of L1-bound). Masked-tile skip kept.
__global__ void __launch_bounds__(64) gemm_xg(const int* __restrict__ seq,
                                              const float* __restrict__ emb,
                                              const float* __restrict__ Wf,
                                              const float* __restrict__ Wb,
                                              const float* __restrict__ bf,
                                              const float* __restrict__ bb,
                                              const int* __restrict__ lengths) {
    int id = blockIdx.x;
    int t   = id / 24;
    int r   = id % 24;
    int bt  = r & 1;               // b half-tile (32 b)
    int nt2 = r >> 1;              // 0..11
    int d   = nt2 / 6;
    int n_base = (nt2 % 6) * 128;

    if (t >= __ldg(&lengths[bt * 32])) return;   // fully-masked tile

    const float* W    = d ? Wb : Wf;
    const float* bias = d ? bb : bf;

    __shared__ float  eT[32][40];        // [k][b] transposed emb tile, padded rows
    __shared__ float2 wd2[32 * 128];     // [k][n] duplicated W pairs (w,w)
    __shared__ int    tok[32];

    int tid = threadIdx.x;
    if (tid < 32) tok[tid] = seq[t * 64 + bt * 32 + tid];

    int nq = tid >> 2;                   // 0..15
    int bq = tid & 3;                    // 0..3
    int n0 = nq * 8, b0 = bq * 8;

    // acc[n][bp]: 8 n x 4 b-pairs, f32x2 packed over (b, b+1)
    ull acc[8][4];
#pragma unroll
    for (int i = 0; i < 8; i++)
#pragma unroll
        for (int q = 0; q < 4; q++) acc[i][q] = 0ull;

    const float4* emb4 = reinterpret_cast<const float4*>(emb);
    const float4* W4   = reinterpret_cast<const float4*>(W);

    for (int k0 = 0; k0 < 256; k0 += 32) {
        __syncthreads();
        // embedding tile (gathered rows) -> eT[k][b]
#pragma unroll
        for (int l = 0; l < 4; l++) {
            int fid = tid + l * 64;
            int b = fid >> 3, kq = fid & 7;
            float4 v = emb4[(size_t)tok[b] * 64 + (k0 >> 2) + kq];
            eT[kq * 4 + 0][b] = v.x; eT[kq * 4 + 1][b] = v.y;
            eT[kq * 4 + 2][b] = v.z; eT[kq * 4 + 3][b] = v.w;
        }
        // W tile, duplicated pairs -> wd2[k][n]
#pragma unroll
        for (int l = 0; l < 16; l++) {
            int fid = tid + l * 64;
            int n = fid >> 3, kq = fid & 7;
            float4 v = W4[(size_t)(n_base + n) * 64 + (k0 >> 2) + kq];
            wd2[(kq * 4 + 0) * 128 + n] = make_float2(v.x, v.x);
            wd2[(kq * 4 + 1) * 128 + n] = make_float2(v.y, v.y);
            wd2[(kq * 4 + 2) * 128 + n] = make_float2(v.z, v.z);
            wd2[(kq * 4 + 3) * 128 + n] = make_float2(v.w, v.w);
        }
        __syncthreads();
#pragma unroll 8
        for (int kk = 0; kk < 32; kk++) {
            // h: 8 b = 4 packed pairs (2x LDS.128)
            ulonglong2 h01 = *reinterpret_cast<const ulonglong2*>(&eT[kk][b0]);
            ulonglong2 h23 = *reinterpret_cast<const ulonglong2*>(&eT[kk][b0 + 4]);
            ull hh[4] = {h01.x, h01.y, h23.x, h23.y};
            // w: 8 n duplicated pairs (4x LDS.128)
            ulonglong2 w01 = *reinterpret_cast<const ulonglong2*>(&wd2[kk * 128 + n0]);
            ulonglong2 w23 = *reinterpret_cast<const ulonglong2*>(&wd2[kk * 128 + n0 + 2]);
            ulonglong2 w45 = *reinterpret_cast<const ulonglong2*>(&wd2[kk * 128 + n0 + 4]);
            ulonglong2 w67 = *reinterpret_cast<const ulonglong2*>(&wd2[kk * 128 + n0 + 6]);
            ull ww[8] = {w01.x, w01.y, w23.x, w23.y, w45.x, w45.y, w67.x, w67.y};
#pragma unroll
            for (int i = 0; i < 8; i++)
#pragma unroll
                for (int q = 0; q < 4; q++)
                    fma2(acc[i][q], hh[q], ww[i]);
        }
    }

    float* out = &g_xg[(size_t)d * T_ * G3 * B_ + (size_t)t * G3 * B_];
#pragma unroll
    for (int i = 0; i < 8; i++) {
        int n = n_base + n0 + i;
        float bv = bias[n];
        float2 p0 = u2f(acc[i][0]), p1 = u2f(acc[i][1]);
        float2 p2 = u2f(acc[i][2]), p3 = u2f(acc[i][3]);
        float4 lo, hi;
        lo.x = p0.x + bv; lo.y = p0.y + bv; lo.z = p1.x + bv; lo.w = p1.y + bv;
        hi.x = p2.x + bv; hi.y = p2.y + bv; hi.z = p3.x + bv; hi.w = p3.y + bv;
        // streaming store: xg is written once, read once much later -> keep out of L2
        __stcs(reinterpret_cast<float4*>(&out[(size_t)n * 64 + bt * 32 + b0]), lo);
        __stcs(reinterpret_cast<float4*>(&out[(size_t)n * 64 + bt * 32 + b0 + 4]), hi);
    }
}

// ---------------- phase 2: grouped bidirectional GRU with self-tagged h exchange ---------
// (byte-identical to R14: 128 CTAs, tagged 8B words, R8 spin shape, atomicAdd y-fusion)
__global__ void __launch_bounds__(256, 1)
recur_kernel(const float* __restrict__ Whh_f,
             const float* __restrict__ Whh_b,
             const float* __restrict__ bhh_f,
             const float* __restrict__ bhh_b,
             const int* __restrict__ lengths,
             float* __restrict__ out) {
    extern __shared__ float sm[];
    float* red0 = sm;                       // [8][24][33]  6336 floats
    float* red1 = sm + 6336;                // parity double buffer
    float* hsm  = sm + 12672;               // [warp8][b8][36] 2304 floats

    int bid = blockIdx.x;
    int d  = bid >> 6;
    int rm = bid & 63;
    int bg = rm >> 3;       // batch group 0..7
    int r  = rm & 7;        // j group 0..7
    const float* Whh = d ? Whh_b : Whh_f;
    const float* bhh = d ? bhh_b : bhh_f;

    int tid = threadIdx.x;
    int kh = tid >> 5;
    int jl = tid & 31;
    int j  = r * 32 + jl;
    int kbase = kh * 32;
    int jl2 = tid >> 3;
    int b2  = tid & 7;
    int j2  = r * 32 + jl2;
    int bglob = bg * 8 + b2;

    ull w0[16], w1[16], w2[16];
    {
        const ulonglong2* W0 = reinterpret_cast<const ulonglong2*>(
            Whh + (size_t)(0 * 256 + j) * 256 + kbase);
        const ulonglong2* W1 = reinterpret_cast<const ulonglong2*>(
            Whh + (size_t)(1 * 256 + j) * 256 + kbase);
        const ulonglong2* W2 = reinterpret_cast<const ulonglong2*>(
            Whh + (size_t)(2 * 256 + j) * 256 + kbase);
#pragma unroll
        for (int q = 0; q < 8; q++) {
            ulonglong2 v0 = W0[q]; w0[2 * q] = v0.x; w0[2 * q + 1] = v0.y;
            ulonglong2 v1 = W1[q]; w1[2 * q] = v1.x; w1[2 * q + 1] = v1.y;
            ulonglong2 v2 = W2[q]; w2[2 * q] = v2.x; w2[2 * q + 1] = v2.y;
        }
    }
    float br = bhh[0 * 256 + j2];
    float bz = bhh[1 * 256 + j2];
    float bn = bhh[2 * 256 + j2];
    int len_b = lengths[bglob];

    const float* xgbase = &g_xg[(size_t)d * T_ * G3 * B_];
    float* hw = &hsm[kh * 8 * 36];

    float h_reg = 0.f;

    for (int step = 0; step < T_; step++) {
        int t = d ? (T_ - 1 - step) : step;
        int p = step & 1;

        const float* xg = &xgbase[(size_t)t * G3 * B_];
        float xr = __ldcs(&xg[(size_t)(0 * 256 + j2) * 64 + bglob]);
        float xz = __ldcs(&xg[(size_t)(1 * 256 + j2) * 64 + bglob]);
        float xn = __ldcs(&xg[(size_t)(2 * 256 + j2) * 64 + bglob]);

        const ull* base = &g_ht[(((d * 2 + p) * 8) + bg) * (H_ * 8)] + kbase * 8;
        ull v[8];
        unsigned texp = (unsigned)step;
        for (;;) {
#pragma unroll
            for (int i = 0; i < 8; i++) v[i] = ld_relaxed_b64(base + i * 32 + jl);
            unsigned ok = 1u;
#pragma unroll
            for (int i = 0; i < 8; i++) ok &= (unsigned)((unsigned)(v[i] >> 32) == texp);
            if (__all_sync(0xffffffffu, ok)) break;
        }
#pragma unroll
        for (int i = 0; i < 8; i++) {
            int n = i * 32 + jl;
            hw[(n & 7) * 36 + (n >> 3)] = __uint_as_float((unsigned)v[i]);
        }
        __syncwarp();

        float f[3][8];
#pragma unroll
        for (int b = 0; b < 8; b++) {
            const float4* hp4 = reinterpret_cast<const float4*>(&hw[b * 36]);
            float4 hv4[8];
#pragma unroll
            for (int q = 0; q < 8; q++) hv4[q] = hp4[q];
            const ull* hv = reinterpret_cast<const ull*>(hv4);
            ull a0 = 0ull, a1 = 0ull, a2 = 0ull;
#pragma unroll
            for (int kp = 0; kp < 16; kp++) {
                fma2(a0, hv[kp], w0[kp]);
                fma2(a1, hv[kp], w1[kp]);
                fma2(a2, hv[kp], w2[kp]);
            }
            float2 t0 = u2f(a0), t1 = u2f(a1), t2 = u2f(a2);
            f[0][b] = t0.x + t0.y;
            f[1][b] = t1.x + t1.y;
            f[2][b] = t2.x + t2.y;
        }

        float* redw = p ? red1 : red0;
#pragma unroll
        for (int b = 0; b < 8; b++) {
#pragma unroll
            for (int g = 0; g < 3; g++)
                redw[(kh * 24 + b * 3 + g) * 33 + jl] = f[g][b];
        }
        __syncthreads();

        float ar = 0.f, az = 0.f, an = 0.f;
#pragma unroll
        for (int q = 0; q < 8; q++) {
            ar += redw[(q * 24 + b2 * 3 + 0) * 33 + jl2];
            az += redw[(q * 24 + b2 * 3 + 1) * 33 + jl2];
            an += redw[(q * 24 + b2 * 3 + 2) * 33 + jl2];
        }

        float hp = h_reg;
        float rg = 1.f / (1.f + __expf(-(xr + ar + br)));
        float zg = 1.f / (1.f + __expf(-(xz + az + bz)));
        float ng = 2.f / (1.f + __expf(-2.f * (xn + rg * (an + bn)))) - 1.f;
        float hv = ng + zg * (hp - ng);
        bool m = (t < len_b);
        float hnext = m ? hv : hp;
        h_reg = hnext;

        ull* rowout = &g_ht[(((d * 2 + (p ^ 1)) * 8) + bg) * (H_ * 8)];
        ull tv = ((ull)(unsigned)(step + 1) << 32) | (ull)__float_as_uint(hnext);
        st_relaxed_b64(&rowout[j2 * 8 + b2], tv);

        if (m) atomicAdd(&out[((size_t)t * 64 + bglob) * 256 + j2], hv);
    }

    out[(size_t)T_ * B_ * H_ + ((size_t)d * 64 + bglob) * 256 + j2] = h_reg;
}

// ---------------- launcher: init -> gemm -> recur (single stream, graph-safe) ----------
extern "C" void kernel_launch(void* const* d_in, const int* in_sizes, int n_in,
                              void* d_out, int out_size) {
    const int*   seq  = (const int*)  d_in[0];
    const int*   lens = (const int*)  d_in[1];
    const float* emb  = (const float*)d_in[2];
    const float* Wihf = (const float*)d_in[3];
    const float* Whhf = (const float*)d_in[4];
    const float* bihf = (const float*)d_in[5];
    const float* bhhf = (const float*)d_in[6];
    const float* Wihb = (const float*)d_in[7];
    const float* Whhb = (const float*)d_in[8];
    const float* bihb = (const float*)d_in[9];
    const float* bhhb = (const float*)d_in[10];
    float* out = (float*)d_out;

    const int smem_recur = (2 * 6336 + 2304) * 4;   // 59904 B
    cudaFuncSetAttribute(recur_kernel, cudaFuncAttributeMaxDynamicSharedMemorySize, smem_recur);

    init_kernel<<<8192, 256>>>(out);
    gemm_xg<<<T_ * 24, 64>>>(seq, emb, Wihf, Wihb, bihf, bihb, lens);
    recur_kernel<<<128, 256, smem_recur>>>(Whhf, Whhb, bhhf, bhhb, lens, out);
}